// round 2
// baseline (speedup 1.0000x reference)
#include <cuda_runtime.h>
#include <stdint.h>

// Problem constants
#define B_   4
#define H_   8
#define N_   2048
#define DV_  64
#define BH_  (B_ * H_)            // 32
#define COLS_ (BH_ * DV_)         // 2048 independent sort columns
#define OUT_ELEMS (BH_ * (size_t)N_ * DV_)   // 4,194,304 floats for 'out'
#define ATTN_ELEMS ((size_t)BH_ * N_ * N_)   // 134,217,728 floats for 'attn'

// ---------------- scratch (device globals; no allocations allowed) ----------
__device__ uint32_t g_key [COLS_ * N_];   // sortable-transformed v, [bh][d][i]  (16MB)
__device__ float    g_vs  [COLS_ * N_];   // sorted values,          [bh][d][r]  (16MB)
__device__ uint16_t g_inv [COLS_ * N_];   // rank of orig index i = inv(p_d)[i]  (8MB)
__device__ uint16_t g_p0  [BH_  * N_];    // p_0[r] (argsort of column d=0)      (128KB)
__device__ float    g_outt[COLS_ * N_];   // out in [bh][d][i] layout            (16MB)

// float <-> order-preserving uint32
__device__ __forceinline__ uint32_t f2sort(float x) {
    uint32_t u = __float_as_uint(x);
    return u ^ ((u & 0x80000000u) ? 0xFFFFFFFFu : 0x80000000u);
}
__device__ __forceinline__ float sort2f(uint32_t u) {
    u ^= (u & 0x80000000u) ? 0x80000000u : 0xFFFFFFFFu;
    return __uint_as_float(u);
}

// ---------------- 1) transpose v [bh][i][d] -> g_key [bh][d][i] (+transform) -
__global__ void k_transpose_in(const float* __restrict__ v) {
    __shared__ float tile[32][33];
    int bh = blockIdx.z;
    int i0 = blockIdx.x * 32;
    int d0 = blockIdx.y * 32;
    int tx = threadIdx.x, ty = threadIdx.y;     // block (32,8)
    const float* src = v + (size_t)bh * N_ * DV_;
#pragma unroll
    for (int r = 0; r < 32; r += 8)
        tile[ty + r][tx] = src[(size_t)(i0 + ty + r) * DV_ + (d0 + tx)];
    __syncthreads();
    uint32_t* dst = g_key + (size_t)bh * DV_ * N_;
#pragma unroll
    for (int r = 0; r < 32; r += 8)
        dst[(size_t)(d0 + ty + r) * N_ + (i0 + tx)] = f2sort(tile[tx][ty + r]);
}

// ---------------- 2) fused: per-column bitonic sort + attn zero-fill --------
// grid = 4096: even blocks sort column (blockIdx>>1); odd blocks zero a
// 256KB slice of attn. Fill (DRAM-bound) overlaps sort (shfl/ALU-bound).
//
// Element->thread mapping: e = warp*256 + r*32 + lane   (8 elems/thread)
//   j in {1,2,4,8,16}  : shfl_xor(j)           (lane bits)
//   j in {32,64,128}   : register pair (r, r^(j>>5))
//   j in {256,512,1024}: smem exchange — lane-consecutive u64, conflict-free
// Packed (key<<32 | idx) gives unique keys => stable argsort.
__global__ __launch_bounds__(256) void k_sortfill(float* __restrict__ attn) {
    const int b = blockIdx.x;
    if (b & 1) {
        const int per4 = (int)(ATTN_ELEMS / 2048 / 4);   // 16384 float4
        float4* p = reinterpret_cast<float4*>(attn) + (size_t)(b >> 1) * per4;
        const float4 z = make_float4(0.f, 0.f, 0.f, 0.f);
#pragma unroll 4
        for (int i = threadIdx.x; i < per4; i += 256) p[i] = z;
        return;
    }
    const int col  = b >> 1;
    const int t    = threadIdx.x;
    const int lane = t & 31;
    const int warp = t >> 5;
    const uint32_t* __restrict__ key = g_key + (size_t)col * N_;

    uint64_t x[8];
#pragma unroll
    for (int r = 0; r < 8; r++) {
        int e = warp * 256 + r * 32 + lane;
        x[r] = ((uint64_t)key[e] << 32) | (uint32_t)e;
    }

    __shared__ uint64_t s[N_];

    for (int k = 2; k <= N_; k <<= 1) {
        for (int j = k >> 1; j > 0; j >>= 1) {
            if (j >= 256) {
#pragma unroll
                for (int r = 0; r < 8; r++)
                    s[warp * 256 + r * 32 + lane] = x[r];
                __syncthreads();
#pragma unroll
                for (int r = 0; r < 8; r++) {
                    int e = warp * 256 + r * 32 + lane;
                    uint64_t y = s[e ^ j];
                    bool keepmin = (((e & j) == 0) == ((e & k) == 0));
                    uint64_t mn = x[r] < y ? x[r] : y;
                    uint64_t mx = x[r] < y ? y : x[r];
                    x[r] = keepmin ? mn : mx;
                }
                __syncthreads();
            } else if (j >= 32) {
                int rj = j >> 5;
#pragma unroll
                for (int r = 0; r < 8; r++) {
                    if ((r & rj) == 0) {
                        int e = warp * 256 + r * 32 + lane;
                        bool up = ((e & k) == 0);
                        uint64_t a = x[r], c = x[r | rj];
                        uint64_t mn = a < c ? a : c;
                        uint64_t mx = a < c ? c : a;
                        x[r]      = up ? mn : mx;
                        x[r | rj] = up ? mx : mn;
                    }
                }
            } else {
#pragma unroll
                for (int r = 0; r < 8; r++) {
                    int e = warp * 256 + r * 32 + lane;
                    uint64_t y = __shfl_xor_sync(0xffffffffu, x[r], j);
                    bool keepmin = (((lane & j) == 0) == ((e & k) == 0));
                    uint64_t mn = x[r] < y ? x[r] : y;
                    uint64_t mx = x[r] < y ? y : x[r];
                    x[r] = keepmin ? mn : mx;
                }
            }
        }
    }

    // epilogue: element e now holds the rank-e entry
    const int d  = col & 63;
    const int bh = col >> 6;
    float*    __restrict__ vs  = g_vs  + (size_t)col * N_;
    uint16_t* __restrict__ inv = g_inv + (size_t)col * N_;
#pragma unroll
    for (int r = 0; r < 8; r++) {
        int e = warp * 256 + r * 32 + lane;
        uint64_t v64 = x[r];
        uint32_t idx = (uint32_t)v64;
        vs[e] = sort2f((uint32_t)(v64 >> 32));
        inv[idx] = (uint16_t)e;
        if (d == 0) g_p0[bh * N_ + e] = (uint16_t)idx;
    }
}

// ---------------- 3) out_t[bh][d][i] = vs[bh][d][ inv[bh][(d+1)%64][i] ] ----
__global__ void k_gather() {
    __shared__ float svs[N_];
    const int col = blockIdx.x;            // bh*64 + d
    const int bh = col >> 6, d = col & 63;
    const int d1 = (d + 1) & 63;
    const float*    vs   = g_vs  + (size_t)col * N_;
    const uint16_t* inv1 = g_inv + (size_t)(bh * DV_ + d1) * N_;
    float*          ot   = g_outt + (size_t)col * N_;

    for (int i = threadIdx.x; i < N_; i += blockDim.x) svs[i] = vs[i];
    __syncthreads();
    for (int i = threadIdx.x; i < N_; i += blockDim.x)
        ot[i] = svs[inv1[i]];
}

// ---------------- 4) transpose g_outt [bh][d][i] -> out [bh][i][d] ----------
__global__ void k_transpose_out(float* __restrict__ out) {
    __shared__ float tile[32][33];
    int bh = blockIdx.z;
    int i0 = blockIdx.x * 32;
    int d0 = blockIdx.y * 32;
    int tx = threadIdx.x, ty = threadIdx.y;     // block (32,8)
    const float* src = g_outt + (size_t)bh * DV_ * N_;
#pragma unroll
    for (int r = 0; r < 32; r += 8)
        tile[ty + r][tx] = src[(size_t)(d0 + ty + r) * N_ + (i0 + tx)];
    __syncthreads();
    float* dst = out + (size_t)bh * N_ * DV_;
#pragma unroll
    for (int r = 0; r < 32; r += 8)
        dst[(size_t)(i0 + ty + r) * DV_ + (d0 + tx)] = tile[tx][ty + r];
}

// ---------------- 5) attn scatter: attn[bh][i][ p0[inv1[i]] ] = 1 -----------
__global__ void k_attn(float* __restrict__ attn) {
    int gid = blockIdx.x * blockDim.x + threadIdx.x;   // bh*N + i
    int bh = gid >> 11;
    int i  = gid & (N_ - 1);
    int j    = g_inv[(size_t)(bh * DV_ + 1) * N_ + i]; // inv(p_1)[i]
    int aidx = g_p0[bh * N_ + j];                      // p_0[j]
    attn[(size_t)gid * N_ + aidx] = 1.0f;
}

// ---------------- launch -----------------------------------------------------
extern "C" void kernel_launch(void* const* d_in, const int* in_sizes, int n_in,
                              void* d_out, int out_size) {
    (void)in_sizes; (void)n_in; (void)out_size;
    const float* v = (const float*)d_in[2];      // metadata order: q, k, v
    float* out  = (float*)d_out;
    float* attn = out + OUT_ELEMS;

    k_transpose_in <<<dim3(N_ / 32, DV_ / 32, BH_), dim3(32, 8)>>>(v);
    k_sortfill     <<<2 * COLS_, 256>>>(attn);          // sort + zero-fill fused
    k_gather       <<<COLS_, 256>>>();
    k_transpose_out<<<dim3(N_ / 32, DV_ / 32, BH_), dim3(32, 8)>>>(out);
    k_attn         <<<(BH_ * N_) / 256, 256>>>(attn);
}

// round 3
// speedup vs baseline: 1.8502x; 1.8502x over previous
#include <cuda_runtime.h>
#include <stdint.h>

// Problem constants
#define B_   4
#define H_   8
#define N_   2048
#define DV_  64
#define BH_  (B_ * H_)            // 32
#define COLS_ (BH_ * DV_)         // 2048 independent sort columns
#define OUT_ELEMS (BH_ * (size_t)N_ * DV_)   // 4,194,304 floats for 'out'
#define ATTN_ELEMS ((size_t)BH_ * N_ * N_)   // 134,217,728 floats for 'attn'

// ---------------- scratch (device globals; no allocations allowed) ----------
__device__ uint32_t g_key [COLS_ * N_];   // sortable-transformed v, [bh][d][i]
__device__ float    g_vs  [COLS_ * N_];   // sorted values,          [bh][d][r]
__device__ uint16_t g_inv [COLS_ * N_];   // rank of orig index i = inv(p_d)[i]
__device__ uint16_t g_p0  [BH_  * N_];    // p_0[r]
__device__ float    g_outt[COLS_ * N_];   // out in [bh][d][i] layout

// float <-> order-preserving uint32
__device__ __forceinline__ uint32_t f2sort(float x) {
    uint32_t u = __float_as_uint(x);
    return u ^ ((u & 0x80000000u) ? 0xFFFFFFFFu : 0x80000000u);
}
__device__ __forceinline__ float sort2f(uint32_t u) {
    u ^= (u & 0x80000000u) ? 0x80000000u : 0xFFFFFFFFu;
    return __uint_as_float(u);
}

// ---------------- 1) transpose v [bh][i][d] -> g_key [bh][d][i] (+transform) -
__global__ void k_transpose_in(const float* __restrict__ v) {
    __shared__ float tile[32][33];
    int bh = blockIdx.z;
    int i0 = blockIdx.x * 32;
    int d0 = blockIdx.y * 32;
    int tx = threadIdx.x, ty = threadIdx.y;     // block (32,8)
    const float* src = v + (size_t)bh * N_ * DV_;
#pragma unroll
    for (int r = 0; r < 32; r += 8)
        tile[ty + r][tx] = src[(size_t)(i0 + ty + r) * DV_ + (d0 + tx)];
    __syncthreads();
    uint32_t* dst = g_key + (size_t)bh * DV_ * N_;
#pragma unroll
    for (int r = 0; r < 32; r += 8)
        dst[(size_t)(d0 + ty + r) * N_ + (i0 + tx)] = f2sort(tile[tx][ty + r]);
}

// ---------------- bitonic merge tail: stages j = J, J/2, ..., 1 -------------
// All register indices and branch selections are COMPILE-TIME (no spills).
// Element->thread map: e = warp*256 + r*32 + lane  (8 elems/thread, 256 thr)
//   J in {32,64,128}: register pair (r, r+RJ)
//   J in {1..16}    : shfl_xor
// Direction: ascending iff (e & k) == 0 (k is runtime; fine).
template<int J>
__device__ __forceinline__ void merge_tail(uint64_t* x, int lane, int warp, int k) {
    if constexpr (J >= 32) {
        constexpr int RJ = J / 32;
#pragma unroll
        for (int r = 0; r < 8; r++) {
            if ((r & RJ) == 0) {
                int e = warp * 256 + r * 32 + lane;
                bool up = ((e & k) == 0);
                uint64_t a = x[r], c = x[r + RJ];
                uint64_t mn = a < c ? a : c;
                uint64_t mx = a < c ? c : a;
                x[r]      = up ? mn : mx;
                x[r + RJ] = up ? mx : mn;
            }
        }
    } else {
#pragma unroll
        for (int r = 0; r < 8; r++) {
            int e = warp * 256 + r * 32 + lane;
            uint64_t y = __shfl_xor_sync(0xffffffffu, x[r], J);
            bool keepmin = (((lane & J) == 0) == ((e & k) == 0));
            uint64_t mn = x[r] < y ? x[r] : y;
            uint64_t mx = x[r] < y ? y : x[r];
            x[r] = keepmin ? mn : mx;
        }
    }
    if constexpr (J > 1) merge_tail<J / 2>(x, lane, warp, k);
}

// ---------------- 2) fused: per-column bitonic sort + attn zero-fill --------
__global__ __launch_bounds__(256) void k_sortfill(float* __restrict__ attn) {
    const int b = blockIdx.x;
    if (b & 1) {   // fill block: zero a 256KB slice of attn
        const int per4 = (int)(ATTN_ELEMS / 2048 / 4);   // 16384 float4
        float4* p = reinterpret_cast<float4*>(attn) + (size_t)(b >> 1) * per4;
        const float4 z = make_float4(0.f, 0.f, 0.f, 0.f);
#pragma unroll 4
        for (int i = threadIdx.x; i < per4; i += 256) p[i] = z;
        return;
    }
    const int col  = b >> 1;
    const int t    = threadIdx.x;
    const int lane = t & 31;
    const int warp = t >> 5;
    const uint32_t* __restrict__ key = g_key + (size_t)col * N_;

    uint64_t x[8];
#pragma unroll
    for (int r = 0; r < 8; r++) {
        int e = warp * 256 + r * 32 + lane;
        x[r] = ((uint64_t)key[e] << 32) | (uint32_t)e;   // unique keys => stable
    }

    __shared__ uint64_t s[N_];

    // k = 2 .. 256: no cross-warp exchange needed
    merge_tail<1>  (x, lane, warp, 2);
    merge_tail<2>  (x, lane, warp, 4);
    merge_tail<4>  (x, lane, warp, 8);
    merge_tail<8>  (x, lane, warp, 16);
    merge_tail<16> (x, lane, warp, 32);
    merge_tail<32> (x, lane, warp, 64);
    merge_tail<64> (x, lane, warp, 128);
    merge_tail<128>(x, lane, warp, 256);

    // k = 512, 1024, 2048: smem stages (j >= 256), then register/shfl tail
    for (int k = 512; k <= 2048; k <<= 1) {
        for (int j = k >> 1; j >= 256; j >>= 1) {
#pragma unroll
            for (int r = 0; r < 8; r++)
                s[warp * 256 + r * 32 + lane] = x[r];
            __syncthreads();
#pragma unroll
            for (int r = 0; r < 8; r++) {
                int e = warp * 256 + r * 32 + lane;
                uint64_t y = s[e ^ j];
                bool keepmin = (((e & j) == 0) == ((e & k) == 0));
                uint64_t mn = x[r] < y ? x[r] : y;
                uint64_t mx = x[r] < y ? y : x[r];
                x[r] = keepmin ? mn : mx;
            }
            __syncthreads();
        }
        merge_tail<128>(x, lane, warp, k);
    }

    // epilogue: element e holds the rank-e entry
    const int d  = col & 63;
    const int bh = col >> 6;
    float*    __restrict__ vs  = g_vs  + (size_t)col * N_;
    uint16_t* __restrict__ inv = g_inv + (size_t)col * N_;
#pragma unroll
    for (int r = 0; r < 8; r++) {
        int e = warp * 256 + r * 32 + lane;
        uint64_t v64 = x[r];
        uint32_t idx = (uint32_t)v64;
        vs[e] = sort2f((uint32_t)(v64 >> 32));
        inv[idx] = (uint16_t)e;
        if (d == 0) g_p0[bh * N_ + e] = (uint16_t)idx;
    }
}

// ---------------- 3) out_t[bh][d][i] = vs[bh][d][ inv[bh][(d+1)%64][i] ] ----
__global__ void k_gather() {
    __shared__ float svs[N_];
    const int col = blockIdx.x;
    const int bh = col >> 6, d = col & 63;
    const int d1 = (d + 1) & 63;
    const float*    vs   = g_vs  + (size_t)col * N_;
    const uint16_t* inv1 = g_inv + (size_t)(bh * DV_ + d1) * N_;
    float*          ot   = g_outt + (size_t)col * N_;

    for (int i = threadIdx.x; i < N_; i += blockDim.x) svs[i] = vs[i];
    __syncthreads();
    for (int i = threadIdx.x; i < N_; i += blockDim.x)
        ot[i] = svs[inv1[i]];
}

// ---------------- 4) transpose g_outt [bh][d][i] -> out [bh][i][d] ----------
__global__ void k_transpose_out(float* __restrict__ out) {
    __shared__ float tile[32][33];
    int bh = blockIdx.z;
    int i0 = blockIdx.x * 32;
    int d0 = blockIdx.y * 32;
    int tx = threadIdx.x, ty = threadIdx.y;
    const float* src = g_outt + (size_t)bh * DV_ * N_;
#pragma unroll
    for (int r = 0; r < 32; r += 8)
        tile[ty + r][tx] = src[(size_t)(d0 + ty + r) * N_ + (i0 + tx)];
    __syncthreads();
    float* dst = out + (size_t)bh * N_ * DV_;
#pragma unroll
    for (int r = 0; r < 32; r += 8)
        dst[(size_t)(i0 + ty + r) * DV_ + (d0 + tx)] = tile[tx][ty + r];
}

// ---------------- 5) attn scatter: attn[bh][i][ p0[inv1[i]] ] = 1 -----------
__global__ void k_attn(float* __restrict__ attn) {
    int gid = blockIdx.x * blockDim.x + threadIdx.x;   // bh*N + i
    int bh = gid >> 11;
    int i  = gid & (N_ - 1);
    int j    = g_inv[(size_t)(bh * DV_ + 1) * N_ + i]; // inv(p_1)[i]
    int aidx = g_p0[bh * N_ + j];                      // p_0[j]
    attn[(size_t)gid * N_ + aidx] = 1.0f;
}

// ---------------- launch -----------------------------------------------------
extern "C" void kernel_launch(void* const* d_in, const int* in_sizes, int n_in,
                              void* d_out, int out_size) {
    (void)in_sizes; (void)n_in; (void)out_size;
    const float* v = (const float*)d_in[2];      // metadata order: q, k, v
    float* out  = (float*)d_out;
    float* attn = out + OUT_ELEMS;

    k_transpose_in <<<dim3(N_ / 32, DV_ / 32, BH_), dim3(32, 8)>>>(v);
    k_sortfill     <<<2 * COLS_, 256>>>(attn);          // sort + zero-fill fused
    k_gather       <<<COLS_, 256>>>();
    k_transpose_out<<<dim3(N_ / 32, DV_ / 32, BH_), dim3(32, 8)>>>(out);
    k_attn         <<<(BH_ * N_) / 256, 256>>>(attn);
}

// round 4
// speedup vs baseline: 2.2026x; 1.1905x over previous
#include <cuda_runtime.h>
#include <stdint.h>

#define B_   4
#define H_   8
#define N_   2048
#define DV_  64
#define BH_  (B_ * H_)            // 32
#define COLS_ (BH_ * DV_)         // 2048 sort columns
#define OUT_ELEMS (BH_ * (size_t)N_ * DV_)
#define ATTN_ELEMS ((size_t)BH_ * N_ * N_)

// ---------------- scratch ----------------------------------------------------
__device__ uint32_t g_key [COLS_ * N_];   // sortable v, [bh][d][i]
__device__ float    g_vs  [COLS_ * N_];   // sorted values [bh][d][r]
__device__ uint16_t g_inv [COLS_ * N_];   // rank of orig index i
__device__ uint16_t g_p0  [BH_  * N_];    // p_0[r]

__device__ __forceinline__ uint32_t f2sort(float x) {
    uint32_t u = __float_as_uint(x);
    return u ^ ((u & 0x80000000u) ? 0xFFFFFFFFu : 0x80000000u);
}
__device__ __forceinline__ float sort2f(uint32_t u) {
    u ^= (u & 0x80000000u) ? 0x80000000u : 0xFFFFFFFFu;
    return __uint_as_float(u);
}

// keepmin ? min(a,y) : max(a,y)  — 2 ISETP + 2 SEL form
__device__ __forceinline__ uint64_t cmpsel(uint64_t a, uint64_t y, bool keepmin) {
    return ((y < a) == keepmin) ? y : a;
}

// ---------------- 1) transpose v [bh][i][d] -> g_key [bh][d][i] --------------
__global__ void k_transpose_in(const float* __restrict__ v) {
    __shared__ float tile[32][33];
    int bh = blockIdx.z;
    int i0 = blockIdx.x * 32;
    int d0 = blockIdx.y * 32;
    int tx = threadIdx.x, ty = threadIdx.y;     // (32,8)
    const float* src = v + (size_t)bh * N_ * DV_;
#pragma unroll
    for (int r = 0; r < 32; r += 8)
        tile[ty + r][tx] = src[(size_t)(i0 + ty + r) * DV_ + (d0 + tx)];
    __syncthreads();
    uint32_t* dst = g_key + (size_t)bh * DV_ * N_;
#pragma unroll
    for (int r = 0; r < 32; r += 8)
        dst[(size_t)(d0 + ty + r) * N_ + (i0 + tx)] = f2sort(tile[tx][ty + r]);
}

// ---------------- bitonic merge tail, compile-time J -------------------------
// e = warp*256 + r*32 + lane  (8 elems/thread, 256 threads)
template<int J>
__device__ __forceinline__ void merge_tail(uint64_t* x, int lane, int warp, int k) {
    if constexpr (J >= 32) {
        constexpr int RJ = J / 32;
#pragma unroll
        for (int r = 0; r < 8; r++) {
            if ((r & RJ) == 0) {
                int e = warp * 256 + r * 32 + lane;
                bool up = ((e & k) == 0);
                uint64_t a = x[r], c = x[r + RJ];
                uint64_t mn = a < c ? a : c;
                uint64_t mx = a < c ? c : a;
                x[r]      = up ? mn : mx;
                x[r + RJ] = up ? mx : mn;
            }
        }
    } else {
#pragma unroll
        for (int r = 0; r < 8; r++) {
            int e = warp * 256 + r * 32 + lane;
            uint64_t y = __shfl_xor_sync(0xffffffffu, x[r], J);
            bool keepmin = (((lane & J) == 0) == ((e & k) == 0));
            x[r] = cmpsel(x[r], y, keepmin);
        }
    }
    if constexpr (J > 1) merge_tail<J / 2>(x, lane, warp, k);
}

// ---------------- 2) fused bitonic sort + attn zero-fill ---------------------
__global__ __launch_bounds__(256) void k_sortfill(float* __restrict__ attn) {
    const int b = blockIdx.x;
    if (b & 1) {   // fill: zero a 256KB slice of attn
        const int per4 = (int)(ATTN_ELEMS / 2048 / 4);   // 16384 float4
        float4* p = reinterpret_cast<float4*>(attn) + (size_t)(b >> 1) * per4;
        const float4 z = make_float4(0.f, 0.f, 0.f, 0.f);
#pragma unroll 4
        for (int i = threadIdx.x; i < per4; i += 256) p[i] = z;
        return;
    }
    const int col  = b >> 1;
    const int lane = threadIdx.x & 31;
    const int warp = threadIdx.x >> 5;
    const uint32_t* __restrict__ key = g_key + (size_t)col * N_;

    uint64_t x[8];
#pragma unroll
    for (int r = 0; r < 8; r++) {
        int e = warp * 256 + r * 32 + lane;
        x[r] = ((uint64_t)key[e] << 32) | (uint32_t)e;   // unique => stable
    }

    __shared__ uint64_t s[N_];

    merge_tail<1>  (x, lane, warp, 2);
    merge_tail<2>  (x, lane, warp, 4);
    merge_tail<4>  (x, lane, warp, 8);
    merge_tail<8>  (x, lane, warp, 16);
    merge_tail<16> (x, lane, warp, 32);
    merge_tail<32> (x, lane, warp, 64);
    merge_tail<64> (x, lane, warp, 128);
    merge_tail<128>(x, lane, warp, 256);

    for (int k = 512; k <= 2048; k <<= 1) {
        for (int j = k >> 1; j >= 256; j >>= 1) {
#pragma unroll
            for (int r = 0; r < 8; r++)
                s[warp * 256 + r * 32 + lane] = x[r];
            __syncthreads();
#pragma unroll
            for (int r = 0; r < 8; r++) {
                int e = warp * 256 + r * 32 + lane;
                uint64_t y = s[e ^ j];
                bool keepmin = (((e & j) == 0) == ((e & k) == 0));
                x[r] = cmpsel(x[r], y, keepmin);
            }
            __syncthreads();
        }
        merge_tail<128>(x, lane, warp, k);
    }

    const int d  = col & 63;
    const int bh = col >> 6;
    float*    __restrict__ vs  = g_vs  + (size_t)col * N_;
    uint16_t* __restrict__ inv = g_inv + (size_t)col * N_;
#pragma unroll
    for (int r = 0; r < 8; r++) {
        int e = warp * 256 + r * 32 + lane;
        uint64_t v64 = x[r];
        uint32_t idx = (uint32_t)v64;
        vs[e] = sort2f((uint32_t)(v64 >> 32));
        inv[idx] = (uint16_t)e;
        if (d == 0) g_p0[bh * N_ + e] = (uint16_t)idx;
    }
}

// ---------------- 3) attn scatter: attn[bh][i][ p0[inv1[i]] ] = 1 ------------
__global__ void k_attn(float* __restrict__ attn) {
    int gid = blockIdx.x * blockDim.x + threadIdx.x;   // bh*N + i
    int bh = gid >> 11;
    int i  = gid & (N_ - 1);
    int j    = g_inv[(size_t)(bh * DV_ + 1) * N_ + i];
    int aidx = g_p0[bh * N_ + j];
    attn[(size_t)gid * N_ + aidx] = 1.0f;
}

// ---------------- 4) fused gather + transpose: out[bh][i][d] -----------------
// block = (dgroup of 16 d, bh). smem: 16 vs columns (128KB) + inv tile.
// out[i, d] = vs_d[ inv_{(d+1)&63}[i] ]
__global__ __launch_bounds__(256) void k_gather_t(float* __restrict__ out) {
    const int bh = blockIdx.y;
    const int d0 = blockIdx.x * 16;
    const int t  = threadIdx.x;

    __shared__ float    svs [16 * N_];          // 128KB
    __shared__ uint16_t sinv[16][256 + 8];      // ~8.3KB

    // load 16 sorted-value columns
#pragma unroll
    for (int d = 0; d < 16; d++)
        for (int i = t; i < N_; i += 256)
            svs[d * N_ + i] = g_vs[(size_t)(bh * DV_ + d0 + d) * N_ + i];

    const int dd = t & 15;         // this thread's d within the group
    const int iw = t >> 4;         // 0..15: row within 16-row microtile
    float* obase = out + (size_t)bh * N_ * DV_ + d0 + dd;

    for (int it = 0; it < 8; it++) {           // i-tiles of 256
        const int i0 = it * 256;
        __syncthreads();
        // stage inv for the 16 needed columns (d1 = d0+d+1 mod 64), coalesced
#pragma unroll
        for (int d = 0; d < 16; d++) {
            int d1 = (d0 + d + 1) & 63;
            sinv[d][t] = g_inv[(size_t)(bh * DV_ + d1) * N_ + i0 + t];
        }
        __syncthreads();
        // each thread: fixed d = dd, rows iw, iw+16, ..., iw+240
#pragma unroll
        for (int rr = 0; rr < 16; rr++) {
            int ii = rr * 16 + iw;
            int rank = sinv[dd][ii];
            obase[(size_t)(i0 + ii) * DV_] = svs[dd * N_ + rank];
        }
    }
}

// ---------------- launch ------------------------------------------------------
extern "C" void kernel_launch(void* const* d_in, const int* in_sizes, int n_in,
                              void* d_out, int out_size) {
    (void)in_sizes; (void)n_in; (void)out_size;
    const float* v = (const float*)d_in[2];      // order: q, k, v
    float* out  = (float*)d_out;
    float* attn = out + OUT_ELEMS;

    k_transpose_in <<<dim3(N_ / 32, DV_ / 32, BH_), dim3(32, 8)>>>(v);
    k_sortfill     <<<2 * COLS_, 256>>>(attn);
    k_attn         <<<(BH_ * N_) / 256, 256>>>(attn);
    k_gather_t     <<<dim3(DV_ / 16, BH_), 256>>>(out);
}

// round 5
// speedup vs baseline: 2.3272x; 1.0566x over previous
#include <cuda_runtime.h>
#include <stdint.h>

#define B_   4
#define H_   8
#define N_   2048
#define DV_  64
#define BH_  (B_ * H_)            // 32
#define COLS_ (BH_ * DV_)         // 2048 sort columns
#define OUT_ELEMS (BH_ * (size_t)N_ * DV_)
#define ATTN_ELEMS ((size_t)BH_ * N_ * N_)

// ---------------- scratch ----------------------------------------------------
__device__ uint32_t g_key [COLS_ * N_];   // sortable v, [bh][d][i]
__device__ float    g_vs  [COLS_ * N_];   // sorted values [bh][d][r]
__device__ uint16_t g_inv [COLS_ * N_];   // rank of orig index i
__device__ uint16_t g_p0  [BH_  * N_];    // p_0[r]

__device__ __forceinline__ uint32_t f2sort(float x) {
    uint32_t u = __float_as_uint(x);
    return u ^ ((u & 0x80000000u) ? 0xFFFFFFFFu : 0x80000000u);
}
__device__ __forceinline__ float sort2f(uint32_t u) {
    u ^= (u & 0x80000000u) ? 0x80000000u : 0xFFFFFFFFu;
    return __uint_as_float(u);
}
__device__ __forceinline__ uint64_t cmpsel(uint64_t a, uint64_t y, bool keepmin) {
    return ((y < a) == keepmin) ? y : a;
}

// ---------------- 1) transpose v [bh][i][d] -> g_key [bh][d][i] --------------
__global__ void k_transpose_in(const float* __restrict__ v) {
    __shared__ float tile[32][33];
    int bh = blockIdx.z;
    int i0 = blockIdx.x * 32;
    int d0 = blockIdx.y * 32;
    int tx = threadIdx.x, ty = threadIdx.y;     // (32,8)
    const float* src = v + (size_t)bh * N_ * DV_;
#pragma unroll
    for (int r = 0; r < 32; r += 8)
        tile[ty + r][tx] = src[(size_t)(i0 + ty + r) * DV_ + (d0 + tx)];
    __syncthreads();
    uint32_t* dst = g_key + (size_t)bh * DV_ * N_;
#pragma unroll
    for (int r = 0; r < 32; r += 8)
        dst[(size_t)(d0 + ty + r) * N_ + (i0 + tx)] = f2sort(tile[tx][ty + r]);
}

// ---------------- bitonic merge tail, compile-time J -------------------------
// NEW map: e = warp*256 + lane*8 + r   (r = low 3 bits)
//   J in {1,2,4}   : intra-thread register pair (r, r+J)
//   J in {8..128}  : shfl_xor(lane bit J/8)
template<int J>
__device__ __forceinline__ void merge_tail(uint64_t* x, int lane, int warp, int k) {
    if constexpr (J >= 8) {
        constexpr int LJ = J / 8;
#pragma unroll
        for (int r = 0; r < 8; r++) {
            int e = warp * 256 + lane * 8 + r;
            uint64_t y = __shfl_xor_sync(0xffffffffu, x[r], LJ);
            bool keepmin = (((lane & LJ) == 0) == ((e & k) == 0));
            x[r] = cmpsel(x[r], y, keepmin);
        }
    } else {
#pragma unroll
        for (int r = 0; r < 8; r++) {
            if ((r & J) == 0) {
                int e = warp * 256 + lane * 8 + r;
                bool up = ((e & k) == 0);
                uint64_t a = x[r], c = x[r + J];
                uint64_t mn = a < c ? a : c;
                uint64_t mx = a < c ? c : a;
                x[r]     = up ? mn : mx;
                x[r + J] = up ? mx : mn;
            }
        }
    }
    if constexpr (J > 1) merge_tail<J / 2>(x, lane, warp, k);
}

// ---------------- 2) fused bitonic sort + attn zero-fill ---------------------
// Padded smem groups (stride 10 u64): 16B-aligned vector ld/st, conflict-free.
__global__ __launch_bounds__(256) void k_sortfill(float* __restrict__ attn) {
    const int b = blockIdx.x;
    if (b & 1) {   // fill: zero a 256KB slice of attn
        const int per4 = (int)(ATTN_ELEMS / 2048 / 4);   // 16384 float4
        float4* p = reinterpret_cast<float4*>(attn) + (size_t)(b >> 1) * per4;
        const float4 z = make_float4(0.f, 0.f, 0.f, 0.f);
#pragma unroll 4
        for (int i = threadIdx.x; i < per4; i += 256) p[i] = z;
        return;
    }
    const int col  = b >> 1;
    const int lane = threadIdx.x & 31;
    const int warp = threadIdx.x >> 5;
    const int g    = warp * 32 + lane;            // group id = e>>3
    const int ebase = g * 8;
    const uint32_t* __restrict__ key = g_key + (size_t)col * N_;

    uint64_t x[8];
    {   // vectorized load: 8 consecutive keys
        uint4 k0 = *reinterpret_cast<const uint4*>(key + ebase);
        uint4 k1 = *reinterpret_cast<const uint4*>(key + ebase + 4);
        x[0] = ((uint64_t)k0.x << 32) | (uint32_t)(ebase + 0);
        x[1] = ((uint64_t)k0.y << 32) | (uint32_t)(ebase + 1);
        x[2] = ((uint64_t)k0.z << 32) | (uint32_t)(ebase + 2);
        x[3] = ((uint64_t)k0.w << 32) | (uint32_t)(ebase + 3);
        x[4] = ((uint64_t)k1.x << 32) | (uint32_t)(ebase + 4);
        x[5] = ((uint64_t)k1.y << 32) | (uint32_t)(ebase + 5);
        x[6] = ((uint64_t)k1.z << 32) | (uint32_t)(ebase + 6);
        x[7] = ((uint64_t)k1.w << 32) | (uint32_t)(ebase + 7);
    }

    __shared__ uint64_t s[10 * 256];   // 20KB, stride-10 groups

    merge_tail<1>  (x, lane, warp, 2);
    merge_tail<2>  (x, lane, warp, 4);
    merge_tail<4>  (x, lane, warp, 8);
    merge_tail<8>  (x, lane, warp, 16);
    merge_tail<16> (x, lane, warp, 32);
    merge_tail<32> (x, lane, warp, 64);
    merge_tail<64> (x, lane, warp, 128);
    merge_tail<128>(x, lane, warp, 256);

    for (int k = 512; k <= 2048; k <<= 1) {
        for (int j = k >> 1; j >= 256; j >>= 1) {
#pragma unroll
            for (int r = 0; r < 8; r += 2)
                *reinterpret_cast<ulonglong2*>(&s[10 * g + r]) =
                    make_ulonglong2(x[r], x[r + 1]);
            __syncthreads();
            const int gp = g ^ (j >> 3);
            const bool upperbit = ((g & (j >> 3)) == 0);
            const bool kbit     = ((ebase & k) == 0);   // k>=512: uniform over r
            const bool keepmin  = (upperbit == kbit);
            uint64_t y[8];
#pragma unroll
            for (int r = 0; r < 8; r += 2) {
                ulonglong2 t2 = *reinterpret_cast<const ulonglong2*>(&s[10 * gp + r]);
                y[r] = t2.x; y[r + 1] = t2.y;
            }
#pragma unroll
            for (int r = 0; r < 8; r++)
                x[r] = cmpsel(x[r], y[r], keepmin);
            __syncthreads();
        }
        merge_tail<128>(x, lane, warp, k);
    }

    // epilogue: element e holds rank-e entry
    const int d  = col & 63;
    const int bh = col >> 6;
    float*    __restrict__ vs  = g_vs  + (size_t)col * N_;
    uint16_t* __restrict__ inv = g_inv + (size_t)col * N_;
    {   // vectorized sorted-value store
        float4 f0 = make_float4(sort2f((uint32_t)(x[0] >> 32)),
                                sort2f((uint32_t)(x[1] >> 32)),
                                sort2f((uint32_t)(x[2] >> 32)),
                                sort2f((uint32_t)(x[3] >> 32)));
        float4 f1 = make_float4(sort2f((uint32_t)(x[4] >> 32)),
                                sort2f((uint32_t)(x[5] >> 32)),
                                sort2f((uint32_t)(x[6] >> 32)),
                                sort2f((uint32_t)(x[7] >> 32)));
        *reinterpret_cast<float4*>(vs + ebase)     = f0;
        *reinterpret_cast<float4*>(vs + ebase + 4) = f1;
    }
#pragma unroll
    for (int r = 0; r < 8; r++) {
        uint32_t idx = (uint32_t)x[r];
        inv[idx] = (uint16_t)(ebase + r);
        if (d == 0) g_p0[bh * N_ + ebase + r] = (uint16_t)idx;
    }
}

// ---------------- 3) fused gather+transpose (and attn scatter blocks) --------
// grid (8, 33): y<32 -> gather for (bh=y, d-group=x*8); y==32 -> attn scatter.
__global__ __launch_bounds__(512) void k_gather_t(float* __restrict__ out,
                                                  float* __restrict__ attn) {
    if (blockIdx.y == BH_) {   // attn: attn[bh][i][ p0[inv1[i]] ] = 1
        int base = blockIdx.x * 8192;
        for (int m = threadIdx.x; m < 8192; m += 512) {
            int gid = base + m;                 // bh*N + i
            int bh = gid >> 11;
            int i  = gid & (N_ - 1);
            int j    = g_inv[(size_t)(bh * DV_ + 1) * N_ + i];
            int aidx = g_p0[bh * N_ + j];
            attn[(size_t)gid * N_ + aidx] = 1.0f;
        }
        return;
    }
    const int bh = blockIdx.y;
    const int d0 = blockIdx.x * 8;
    const int t  = threadIdx.x;

    __shared__ float    svs [8 * N_];        // 64KB
    __shared__ uint16_t sinv[8][512 + 8];

#pragma unroll
    for (int d = 0; d < 8; d++)
        for (int i = t; i < N_; i += 512)
            svs[d * N_ + i] = g_vs[(size_t)(bh * DV_ + d0 + d) * N_ + i];

    const int dd = t & 7;          // this thread's d
    const int iw = t >> 3;         // 0..63
    float* obase = out + (size_t)bh * N_ * DV_ + d0 + dd;

    for (int it = 0; it < 4; it++) {         // i-tiles of 512
        const int i0 = it * 512;
        __syncthreads();
#pragma unroll
        for (int d = 0; d < 8; d++) {
            int d1 = (d0 + d + 1) & 63;
            sinv[d][t] = g_inv[(size_t)(bh * DV_ + d1) * N_ + i0 + t];
        }
        __syncthreads();
#pragma unroll
        for (int rr = 0; rr < 8; rr++) {
            int ii = rr * 64 + iw;
            int rank = sinv[dd][ii];
            obase[(size_t)(i0 + ii) * DV_] = svs[dd * N_ + rank];
        }
    }
}

// ---------------- launch ------------------------------------------------------
extern "C" void kernel_launch(void* const* d_in, const int* in_sizes, int n_in,
                              void* d_out, int out_size) {
    (void)in_sizes; (void)n_in; (void)out_size;
    const float* v = (const float*)d_in[2];      // order: q, k, v
    float* out  = (float*)d_out;
    float* attn = out + OUT_ELEMS;

    k_transpose_in <<<dim3(N_ / 32, DV_ / 32, BH_), dim3(32, 8)>>>(v);
    k_sortfill     <<<2 * COLS_, 256>>>(attn);
    k_gather_t     <<<dim3(8, BH_ + 1), 512>>>(out, attn);
}

// round 6
// speedup vs baseline: 2.5496x; 1.0956x over previous
#include <cuda_runtime.h>
#include <stdint.h>

#define B_   4
#define H_   8
#define N_   2048
#define DV_  64
#define BH_  (B_ * H_)            // 32
#define COLS_ (BH_ * DV_)         // 2048 sort columns
#define OUT_ELEMS (BH_ * (size_t)N_ * DV_)
#define ATTN_ELEMS ((size_t)BH_ * N_ * N_)

// ---------------- scratch ----------------------------------------------------
__device__ uint32_t g_key [COLS_ * N_];   // sortable v, [bh][d][i]
__device__ float    g_vs  [COLS_ * N_];   // sorted values [bh][d][r]
__device__ uint16_t g_inv [COLS_ * N_];   // rank of orig index i
__device__ uint16_t g_p0  [BH_  * N_];    // p_0[r]

__device__ __forceinline__ uint32_t f2sort(float x) {
    uint32_t u = __float_as_uint(x);
    return u ^ ((u & 0x80000000u) ? 0xFFFFFFFFu : 0x80000000u);
}
__device__ __forceinline__ float sort2f(uint32_t u) {
    u ^= (u & 0x80000000u) ? 0x80000000u : 0xFFFFFFFFu;
    return __uint_as_float(u);
}
__device__ __forceinline__ uint64_t cmpsel(uint64_t a, uint64_t y, bool keepmin) {
    return ((y < a) == keepmin) ? y : a;
}

// ---------------- 1) transpose v [bh][i][d] -> g_key [bh][d][i] --------------
__global__ void k_transpose_in(const float* __restrict__ v) {
    __shared__ float tile[32][33];
    int bh = blockIdx.z;
    int i0 = blockIdx.x * 32;
    int d0 = blockIdx.y * 32;
    int tx = threadIdx.x, ty = threadIdx.y;     // (32,8)
    const float* src = v + (size_t)bh * N_ * DV_;
#pragma unroll
    for (int r = 0; r < 32; r += 8)
        tile[ty + r][tx] = src[(size_t)(i0 + ty + r) * DV_ + (d0 + tx)];
    __syncthreads();
    uint32_t* dst = g_key + (size_t)bh * DV_ * N_;
#pragma unroll
    for (int r = 0; r < 32; r += 8)
        dst[(size_t)(d0 + ty + r) * N_ + (i0 + tx)] = f2sort(tile[tx][ty + r]);
}

// ---------------- bitonic merge tail, compile-time J -------------------------
// map: e = warp*256 + lane*8 + r
//   J in {1,2,4}  : intra-thread register pair (r, r+J)
//   J in {8..128} : shfl_xor(lane bit J/8)
template<int J>
__device__ __forceinline__ void merge_tail(uint64_t* x, int lane, int warp, int k) {
    if constexpr (J >= 8) {
        constexpr int LJ = J / 8;
#pragma unroll
        for (int r = 0; r < 8; r++) {
            int e = warp * 256 + lane * 8 + r;
            uint64_t y = __shfl_xor_sync(0xffffffffu, x[r], LJ);
            bool keepmin = (((lane & LJ) == 0) == ((e & k) == 0));
            x[r] = cmpsel(x[r], y, keepmin);
        }
    } else {
#pragma unroll
        for (int r = 0; r < 8; r++) {
            if ((r & J) == 0) {
                int e = warp * 256 + lane * 8 + r;
                bool up = ((e & k) == 0);
                uint64_t a = x[r], c = x[r + J];
                uint64_t mn = a < c ? a : c;
                uint64_t mx = a < c ? c : a;
                x[r]     = up ? mn : mx;
                x[r + J] = up ? mx : mn;
            }
        }
    }
    if constexpr (J > 1) merge_tail<J / 2>(x, lane, warp, k);
}

// ---------------- 2) fused: bitonic sort + in-block attn zero-fill -----------
// Each block sorts one column AND zero-fills its exclusive 256KB attn slice.
// Fill = 8 chunks of 8 streaming STG.128 per thread, interleaved between
// bitonic phases: stores are fire-and-forget, so DRAM drains under ALU work.
__global__ __launch_bounds__(256) void k_sortfill(float* __restrict__ attn) {
    const int col  = blockIdx.x;
    const int t    = threadIdx.x;
    const int lane = t & 31;
    const int warp = t >> 5;
    const int g    = warp * 32 + lane;
    const int ebase = g * 8;

    float4* __restrict__ fbase =
        reinterpret_cast<float4*>(attn) + (size_t)col * 16384 + t;
    const float4 z = make_float4(0.f, 0.f, 0.f, 0.f);
#define FILL8(c)                                                     \
    {  _Pragma("unroll")                                             \
       for (int s_ = 0; s_ < 8; s_++)                                \
           __stcs(fbase + (c) * 2048 + s_ * 256, z); }

    const uint32_t* __restrict__ key = g_key + (size_t)col * N_;

    FILL8(0)

    uint64_t x[8];
    {
        uint4 k0 = *reinterpret_cast<const uint4*>(key + ebase);
        uint4 k1 = *reinterpret_cast<const uint4*>(key + ebase + 4);
        x[0] = ((uint64_t)k0.x << 32) | (uint32_t)(ebase + 0);
        x[1] = ((uint64_t)k0.y << 32) | (uint32_t)(ebase + 1);
        x[2] = ((uint64_t)k0.z << 32) | (uint32_t)(ebase + 2);
        x[3] = ((uint64_t)k0.w << 32) | (uint32_t)(ebase + 3);
        x[4] = ((uint64_t)k1.x << 32) | (uint32_t)(ebase + 4);
        x[5] = ((uint64_t)k1.y << 32) | (uint32_t)(ebase + 5);
        x[6] = ((uint64_t)k1.z << 32) | (uint32_t)(ebase + 6);
        x[7] = ((uint64_t)k1.w << 32) | (uint32_t)(ebase + 7);
    }

    __shared__ uint64_t s[10 * 256];   // 20KB, stride-10 groups

    merge_tail<1>  (x, lane, warp, 2);
    FILL8(1)
    merge_tail<2>  (x, lane, warp, 4);
    FILL8(2)
    merge_tail<4>  (x, lane, warp, 8);
    FILL8(3)
    merge_tail<8>  (x, lane, warp, 16);
    FILL8(4)
    merge_tail<16> (x, lane, warp, 32);
    FILL8(5)
    merge_tail<32> (x, lane, warp, 64);
    FILL8(6)
    merge_tail<64> (x, lane, warp, 128);
    FILL8(7)
    merge_tail<128>(x, lane, warp, 256);

    for (int k = 512; k <= 2048; k <<= 1) {
        for (int j = k >> 1; j >= 256; j >>= 1) {
#pragma unroll
            for (int r = 0; r < 8; r += 2)
                *reinterpret_cast<ulonglong2*>(&s[10 * g + r]) =
                    make_ulonglong2(x[r], x[r + 1]);
            __syncthreads();
            const int gp = g ^ (j >> 3);
            const bool upperbit = ((g & (j >> 3)) == 0);
            const bool kbit     = ((ebase & k) == 0);
            const bool keepmin  = (upperbit == kbit);
            uint64_t y[8];
#pragma unroll
            for (int r = 0; r < 8; r += 2) {
                ulonglong2 t2 = *reinterpret_cast<const ulonglong2*>(&s[10 * gp + r]);
                y[r] = t2.x; y[r + 1] = t2.y;
            }
#pragma unroll
            for (int r = 0; r < 8; r++)
                x[r] = cmpsel(x[r], y[r], keepmin);
            __syncthreads();
        }
        merge_tail<128>(x, lane, warp, k);
    }

    // epilogue: element e holds rank-e entry
    const int d  = col & 63;
    const int bh = col >> 6;
    float*    __restrict__ vs  = g_vs  + (size_t)col * N_;
    uint16_t* __restrict__ inv = g_inv + (size_t)col * N_;
    {
        float4 f0 = make_float4(sort2f((uint32_t)(x[0] >> 32)),
                                sort2f((uint32_t)(x[1] >> 32)),
                                sort2f((uint32_t)(x[2] >> 32)),
                                sort2f((uint32_t)(x[3] >> 32)));
        float4 f1 = make_float4(sort2f((uint32_t)(x[4] >> 32)),
                                sort2f((uint32_t)(x[5] >> 32)),
                                sort2f((uint32_t)(x[6] >> 32)),
                                sort2f((uint32_t)(x[7] >> 32)));
        *reinterpret_cast<float4*>(vs + ebase)     = f0;
        *reinterpret_cast<float4*>(vs + ebase + 4) = f1;
    }
#pragma unroll
    for (int r = 0; r < 8; r++) {
        uint32_t idx = (uint32_t)x[r];
        inv[idx] = (uint16_t)(ebase + r);
        if (d == 0) g_p0[bh * N_ + ebase + r] = (uint16_t)idx;
    }
#undef FILL8
}

// ---------------- 3) fused gather+transpose (and attn scatter blocks) --------
__global__ __launch_bounds__(512) void k_gather_t(float* __restrict__ out,
                                                  float* __restrict__ attn) {
    if (blockIdx.y == BH_) {   // attn: attn[bh][i][ p0[inv1[i]] ] = 1
        int base = blockIdx.x * 8192;
        for (int m = threadIdx.x; m < 8192; m += 512) {
            int gid = base + m;
            int bh = gid >> 11;
            int i  = gid & (N_ - 1);
            int j    = g_inv[(size_t)(bh * DV_ + 1) * N_ + i];
            int aidx = g_p0[bh * N_ + j];
            attn[(size_t)gid * N_ + aidx] = 1.0f;
        }
        return;
    }
    const int bh = blockIdx.y;
    const int d0 = blockIdx.x * 8;
    const int t  = threadIdx.x;

    __shared__ float    svs [8 * N_];        // 64KB
    __shared__ uint16_t sinv[8][512 + 8];

#pragma unroll
    for (int d = 0; d < 8; d++)
        for (int i = t; i < N_; i += 512)
            svs[d * N_ + i] = g_vs[(size_t)(bh * DV_ + d0 + d) * N_ + i];

    const int dd = t & 7;
    const int iw = t >> 3;
    float* obase = out + (size_t)bh * N_ * DV_ + d0 + dd;

    for (int it = 0; it < 4; it++) {
        const int i0 = it * 512;
        __syncthreads();
#pragma unroll
        for (int d = 0; d < 8; d++) {
            int d1 = (d0 + d + 1) & 63;
            sinv[d][t] = g_inv[(size_t)(bh * DV_ + d1) * N_ + i0 + t];
        }
        __syncthreads();
#pragma unroll
        for (int rr = 0; rr < 8; rr++) {
            int ii = rr * 64 + iw;
            int rank = sinv[dd][ii];
            obase[(size_t)(i0 + ii) * DV_] = svs[dd * N_ + rank];
        }
    }
}

// ---------------- launch ------------------------------------------------------
extern "C" void kernel_launch(void* const* d_in, const int* in_sizes, int n_in,
                              void* d_out, int out_size) {
    (void)in_sizes; (void)n_in; (void)out_size;
    const float* v = (const float*)d_in[2];      // order: q, k, v
    float* out  = (float*)d_out;
    float* attn = out + OUT_ELEMS;

    k_transpose_in <<<dim3(N_ / 32, DV_ / 32, BH_), dim3(32, 8)>>>(v);
    k_sortfill     <<<COLS_, 256>>>(attn);
    k_gather_t     <<<dim3(8, BH_ + 1), 512>>>(out, attn);
}

// round 7
// speedup vs baseline: 2.7666x; 1.0851x over previous
#include <cuda_runtime.h>
#include <stdint.h>

#define B_   4
#define H_   8
#define N_   2048
#define DV_  64
#define BH_  (B_ * H_)            // 32
#define COLS_ (BH_ * DV_)         // 2048 sort columns
#define OUT_ELEMS (BH_ * (size_t)N_ * DV_)
#define ATTN_ELEMS ((size_t)BH_ * N_ * N_)

// ---------------- scratch ----------------------------------------------------
__device__ uint32_t g_key [COLS_ * N_];   // sortable v, [bh][d][i]
__device__ float    g_vs  [COLS_ * N_];   // sorted values [bh][d][r]
__device__ uint16_t g_inv [COLS_ * N_];   // rank of orig index i
__device__ uint16_t g_p0  [BH_  * N_];    // p_0[r]

__device__ __forceinline__ uint32_t f2sort(float x) {
    uint32_t u = __float_as_uint(x);
    return u ^ ((u & 0x80000000u) ? 0xFFFFFFFFu : 0x80000000u);
}
__device__ __forceinline__ float sort2f(uint32_t u) {
    u ^= (u & 0x80000000u) ? 0x80000000u : 0xFFFFFFFFu;
    return __uint_as_float(u);
}
__device__ __forceinline__ uint64_t cmpsel(uint64_t a, uint64_t y, bool keepmin) {
    return ((y < a) == keepmin) ? y : a;
}

// ---------------- 1) transpose v [bh][i][d] -> g_key [bh][d][i] --------------
__global__ void k_transpose_in(const float* __restrict__ v) {
    __shared__ float tile[32][33];
    int bh = blockIdx.z;
    int i0 = blockIdx.x * 32;
    int d0 = blockIdx.y * 32;
    int tx = threadIdx.x, ty = threadIdx.y;     // (32,8)
    const float* src = v + (size_t)bh * N_ * DV_;
#pragma unroll
    for (int r = 0; r < 32; r += 8)
        tile[ty + r][tx] = src[(size_t)(i0 + ty + r) * DV_ + (d0 + tx)];
    __syncthreads();
    uint32_t* dst = g_key + (size_t)bh * DV_ * N_;
#pragma unroll
    for (int r = 0; r < 32; r += 8)
        dst[(size_t)(d0 + ty + r) * N_ + (i0 + tx)] = f2sort(tile[tx][ty + r]);
}

// ---------------- bitonic merge tail, compile-time J -------------------------
// map: e = warp*256 + lane*8 + r
template<int J>
__device__ __forceinline__ void merge_tail(uint64_t* x, int lane, int warp, int k) {
    if constexpr (J >= 8) {
        constexpr int LJ = J / 8;
#pragma unroll
        for (int r = 0; r < 8; r++) {
            int e = warp * 256 + lane * 8 + r;
            uint64_t y = __shfl_xor_sync(0xffffffffu, x[r], LJ);
            bool keepmin = (((lane & LJ) == 0) == ((e & k) == 0));
            x[r] = cmpsel(x[r], y, keepmin);
        }
    } else {
#pragma unroll
        for (int r = 0; r < 8; r++) {
            if ((r & J) == 0) {
                int e = warp * 256 + lane * 8 + r;
                bool up = ((e & k) == 0);
                uint64_t a = x[r], c = x[r + J];
                uint64_t mn = a < c ? a : c;
                uint64_t mx = a < c ? c : a;
                x[r]     = up ? mn : mx;
                x[r + J] = up ? mx : mn;
            }
        }
    }
    if constexpr (J > 1) merge_tail<J / 2>(x, lane, warp, k);
}

// one cross-warp smem exchange stage (j >= 256), runtime j,k
__device__ __forceinline__ void smem_stage(uint64_t* x, uint64_t* s,
                                           int g, int ebase, int j, int k) {
#pragma unroll
    for (int r = 0; r < 8; r += 2)
        *reinterpret_cast<ulonglong2*>(&s[10 * g + r]) =
            make_ulonglong2(x[r], x[r + 1]);
    __syncthreads();
    const int gp = g ^ (j >> 3);
    const bool upperbit = ((g & (j >> 3)) == 0);
    const bool kbit     = ((ebase & k) == 0);
    const bool keepmin  = (upperbit == kbit);
    uint64_t y[8];
#pragma unroll
    for (int r = 0; r < 8; r += 2) {
        ulonglong2 t2 = *reinterpret_cast<const ulonglong2*>(&s[10 * gp + r]);
        y[r] = t2.x; y[r + 1] = t2.y;
    }
#pragma unroll
    for (int r = 0; r < 8; r++)
        x[r] = cmpsel(x[r], y[r], keepmin);
    __syncthreads();
}

// ---------------- 2) fused: bitonic sort + attn zero-fill, spread evenly -----
// Each block sorts one column AND zero-fills its 256KB attn slice via 16
// chunks of 4 streaming STG.128 per thread, spread over the ENTIRE sort
// (including the late smem stages) so store issue tracks DRAM drain rate.
__global__ __launch_bounds__(256) void k_sortfill(float* __restrict__ attn) {
    const int col  = blockIdx.x;
    const int t    = threadIdx.x;
    const int lane = t & 31;
    const int warp = t >> 5;
    const int g    = warp * 32 + lane;
    const int ebase = g * 8;

    float4* __restrict__ fbase =
        reinterpret_cast<float4*>(attn) + (size_t)col * 16384 + t;
    const float4 z = make_float4(0.f, 0.f, 0.f, 0.f);
#define FILL4(c)                                                     \
    {  _Pragma("unroll")                                             \
       for (int s_ = 0; s_ < 4; s_++)                                \
           __stcs(fbase + (c) * 1024 + s_ * 256, z); }

    const uint32_t* __restrict__ key = g_key + (size_t)col * N_;

    FILL4(0)

    uint64_t x[8];
    {
        uint4 k0 = *reinterpret_cast<const uint4*>(key + ebase);
        uint4 k1 = *reinterpret_cast<const uint4*>(key + ebase + 4);
        x[0] = ((uint64_t)k0.x << 32) | (uint32_t)(ebase + 0);
        x[1] = ((uint64_t)k0.y << 32) | (uint32_t)(ebase + 1);
        x[2] = ((uint64_t)k0.z << 32) | (uint32_t)(ebase + 2);
        x[3] = ((uint64_t)k0.w << 32) | (uint32_t)(ebase + 3);
        x[4] = ((uint64_t)k1.x << 32) | (uint32_t)(ebase + 4);
        x[5] = ((uint64_t)k1.y << 32) | (uint32_t)(ebase + 5);
        x[6] = ((uint64_t)k1.z << 32) | (uint32_t)(ebase + 6);
        x[7] = ((uint64_t)k1.w << 32) | (uint32_t)(ebase + 7);
    }

    __shared__ uint64_t s[10 * 256];   // 20KB, stride-10 groups

    merge_tail<1>  (x, lane, warp, 2);
    merge_tail<2>  (x, lane, warp, 4);
    merge_tail<4>  (x, lane, warp, 8);
    FILL4(1)
    merge_tail<8>  (x, lane, warp, 16);
    FILL4(2)
    merge_tail<16> (x, lane, warp, 32);
    FILL4(3)
    merge_tail<32> (x, lane, warp, 64);
    FILL4(4)
    merge_tail<64> (x, lane, warp, 128);
    FILL4(5)
    merge_tail<128>(x, lane, warp, 256);
    FILL4(6)

    // k = 512
    smem_stage(x, s, g, ebase, 256, 512);
    FILL4(7)
    merge_tail<128>(x, lane, warp, 512);
    FILL4(8)
    // k = 1024
    smem_stage(x, s, g, ebase, 512, 1024);
    FILL4(9)
    smem_stage(x, s, g, ebase, 256, 1024);
    FILL4(10)
    merge_tail<128>(x, lane, warp, 1024);
    FILL4(11)
    // k = 2048
    smem_stage(x, s, g, ebase, 1024, 2048);
    FILL4(12)
    smem_stage(x, s, g, ebase, 512, 2048);
    FILL4(13)
    smem_stage(x, s, g, ebase, 256, 2048);
    FILL4(14)
    merge_tail<128>(x, lane, warp, 2048);
    FILL4(15)

    // epilogue: element e holds rank-e entry
    const int d  = col & 63;
    const int bh = col >> 6;
    float*    __restrict__ vs  = g_vs  + (size_t)col * N_;
    uint16_t* __restrict__ inv = g_inv + (size_t)col * N_;
    {
        float4 f0 = make_float4(sort2f((uint32_t)(x[0] >> 32)),
                                sort2f((uint32_t)(x[1] >> 32)),
                                sort2f((uint32_t)(x[2] >> 32)),
                                sort2f((uint32_t)(x[3] >> 32)));
        float4 f1 = make_float4(sort2f((uint32_t)(x[4] >> 32)),
                                sort2f((uint32_t)(x[5] >> 32)),
                                sort2f((uint32_t)(x[6] >> 32)),
                                sort2f((uint32_t)(x[7] >> 32)));
        *reinterpret_cast<float4*>(vs + ebase)     = f0;
        *reinterpret_cast<float4*>(vs + ebase + 4) = f1;
    }
#pragma unroll
    for (int r = 0; r < 8; r++) {
        uint32_t idx = (uint32_t)x[r];
        inv[idx] = (uint16_t)(ebase + r);
        if (d == 0) g_p0[bh * N_ + ebase + r] = (uint16_t)idx;
    }
#undef FILL4
}

// ---------------- 3) fused gather+transpose (and attn scatter blocks) --------
__global__ __launch_bounds__(512) void k_gather_t(float* __restrict__ out,
                                                  float* __restrict__ attn) {
    if (blockIdx.y == BH_) {   // attn: attn[bh][i][ p0[inv1[i]] ] = 1
        int base = blockIdx.x * 8192;
        for (int m = threadIdx.x; m < 8192; m += 512) {
            int gid = base + m;
            int bh = gid >> 11;
            int i  = gid & (N_ - 1);
            int j    = g_inv[(size_t)(bh * DV_ + 1) * N_ + i];
            int aidx = g_p0[bh * N_ + j];
            attn[(size_t)gid * N_ + aidx] = 1.0f;
        }
        return;
    }
    const int bh = blockIdx.y;
    const int d0 = blockIdx.x * 8;
    const int t  = threadIdx.x;

    __shared__ float    svs [8 * N_];        // 64KB
    __shared__ uint16_t sinv[8][512 + 8];

#pragma unroll
    for (int d = 0; d < 8; d++)
        for (int i = t; i < N_; i += 512)
            svs[d * N_ + i] = g_vs[(size_t)(bh * DV_ + d0 + d) * N_ + i];

    const int dd = t & 7;
    const int iw = t >> 3;
    float* obase = out + (size_t)bh * N_ * DV_ + d0 + dd;

    for (int it = 0; it < 4; it++) {
        const int i0 = it * 512;
        __syncthreads();
#pragma unroll
        for (int d = 0; d < 8; d++) {
            int d1 = (d0 + d + 1) & 63;
            sinv[d][t] = g_inv[(size_t)(bh * DV_ + d1) * N_ + i0 + t];
        }
        __syncthreads();
#pragma unroll
        for (int rr = 0; rr < 8; rr++) {
            int ii = rr * 64 + iw;
            int rank = sinv[dd][ii];
            obase[(size_t)(i0 + ii) * DV_] = svs[dd * N_ + rank];
        }
    }
}

// ---------------- launch ------------------------------------------------------
extern "C" void kernel_launch(void* const* d_in, const int* in_sizes, int n_in,
                              void* d_out, int out_size) {
    (void)in_sizes; (void)n_in; (void)out_size;
    const float* v = (const float*)d_in[2];      // order: q, k, v
    float* out  = (float*)d_out;
    float* attn = out + OUT_ELEMS;

    k_transpose_in <<<dim3(N_ / 32, DV_ / 32, BH_), dim3(32, 8)>>>(v);
    k_sortfill     <<<COLS_, 256>>>(attn);
    k_gather_t     <<<dim3(8, BH_ + 1), 512>>>(out, attn);
}